// round 1
// baseline (speedup 1.0000x reference)
#include <cuda_runtime.h>
#include <cuda_bf16.h>
#include <math.h>

#define D_MODEL 1024
#define NHEAD   16
#define DK      64
#define SEQ     2048
#define BATCH   2
#define MTOT    (BATCH * SEQ)          // 4096
#define BH      (BATCH * NHEAD)        // 32

// Scratch (device globals: allocation-free)
__device__ float g_q[MTOT * D_MODEL];     // [BH, S, DK] head layout
__device__ float g_k[MTOT * D_MODEL];
__device__ float g_v[MTOT * D_MODEL];
__device__ float g_attn[MTOT * D_MODEL];  // [B, S, D] plain layout

// ---------------------------------------------------------------------------
// GEMM: C = X[4096,1024] @ W[1024,1024] + b  (W stored [in,out] row-major)
// 128x128 tile, 256 threads, 8x8 register blocking, k-step 16.
// HEAD=true: scatter to [B,H,S,DK] layout; else plain [M,N].
// ---------------------------------------------------------------------------
template <bool HEAD>
__global__ __launch_bounds__(256)
void gemm_bias_k(const float* __restrict__ X, const float* __restrict__ W,
                 const float* __restrict__ bias, float* __restrict__ C)
{
    __shared__ float As[16][132];   // [k][m], padded
    __shared__ float Bs[16][128];   // [k][n]

    const int tid = threadIdx.x;
    const int tx = tid & 15, ty = tid >> 4;
    const int m0 = blockIdx.y * 128;
    const int n0 = blockIdx.x * 128;

    float acc[8][8];
    #pragma unroll
    for (int i = 0; i < 8; i++)
        #pragma unroll
        for (int j = 0; j < 8; j++) acc[i][j] = 0.f;

    for (int k0 = 0; k0 < D_MODEL; k0 += 16) {
        // Load A tile (128 rows x 16 k) transposed into As[k][m]
        #pragma unroll
        for (int i = 0; i < 2; i++) {
            int lin = tid + i * 256;           // 0..511 float4s
            int r  = lin >> 2;
            int c4 = (lin & 3) * 4;
            float4 v = *(const float4*)&X[(size_t)(m0 + r) * D_MODEL + k0 + c4];
            As[c4 + 0][r] = v.x;
            As[c4 + 1][r] = v.y;
            As[c4 + 2][r] = v.z;
            As[c4 + 3][r] = v.w;
        }
        // Load B tile (16 k x 128 n)
        #pragma unroll
        for (int i = 0; i < 2; i++) {
            int lin = tid + i * 256;
            int r  = lin >> 5;
            int c4 = (lin & 31) * 4;
            *(float4*)&Bs[r][c4] =
                *(const float4*)&W[(size_t)(k0 + r) * D_MODEL + n0 + c4];
        }
        __syncthreads();

        #pragma unroll
        for (int kk = 0; kk < 16; kk++) {
            float a[8], b[8];
            *(float4*)&a[0] = *(float4*)&As[kk][ty * 8];
            *(float4*)&a[4] = *(float4*)&As[kk][ty * 8 + 4];
            *(float4*)&b[0] = *(float4*)&Bs[kk][tx * 8];
            *(float4*)&b[4] = *(float4*)&Bs[kk][tx * 8 + 4];
            #pragma unroll
            for (int i = 0; i < 8; i++)
                #pragma unroll
                for (int j = 0; j < 8; j++)
                    acc[i][j] += a[i] * b[j];
        }
        __syncthreads();
    }

    // Epilogue: bias + store
    #pragma unroll
    for (int i = 0; i < 8; i++) {
        int m = m0 + ty * 8 + i;
        int b_idx = m >> 11;          // /2048
        int s_idx = m & 2047;
        #pragma unroll
        for (int j = 0; j < 8; j++) {
            int n = n0 + tx * 8 + j;
            float v = acc[i][j] + bias[n];
            if (HEAD) {
                int h = n >> 6, d = n & 63;
                C[(size_t)(b_idx * NHEAD + h) * (SEQ * DK) + (size_t)s_idx * DK + d] = v;
            } else {
                C[(size_t)m * D_MODEL + n] = v;
            }
        }
    }
}

// ---------------------------------------------------------------------------
// Flash attention: per block = (bh, q-tile of 128 rows). 128 threads, one
// q row per thread (q + acc in registers). Streams K/V in 64-key smem tiles.
// Writes attn output back in [B, S, D] layout for the output projection.
// ---------------------------------------------------------------------------
__global__ __launch_bounds__(128)
void flash_attn_k(const float* __restrict__ Qh, const float* __restrict__ Kh,
                  const float* __restrict__ Vh, float* __restrict__ Out)
{
    __shared__ float Ks[64][64];
    __shared__ float Vs[64][64];

    const int t  = threadIdx.x;
    const int qt = blockIdx.x & 15;      // 16 q-tiles of 128
    const int bh = blockIdx.x >> 4;      // 0..31
    const int row = qt * 128 + t;

    const float* qp = Qh + ((size_t)bh * SEQ + row) * DK;
    float q[DK];
    #pragma unroll
    for (int i = 0; i < DK / 4; i++)
        *(float4*)&q[i * 4] = *(const float4*)&qp[i * 4];

    float mval = -1e30f, l = 0.f;
    float acc[DK];
    #pragma unroll
    for (int d = 0; d < DK; d++) acc[d] = 0.f;

    const float scale = 0.125f;  // 1/sqrt(64)

    for (int kt = 0; kt < SEQ / 64; kt++) {
        const float* kp = Kh + ((size_t)bh * SEQ + kt * 64) * DK;
        const float* vp = Vh + ((size_t)bh * SEQ + kt * 64) * DK;
        #pragma unroll
        for (int i = 0; i < 8; i++) {
            int lin = t + i * 128;     // 0..1023 float4s
            int r = lin >> 4;
            int c = (lin & 15) * 4;
            *(float4*)&Ks[r][c] = *(const float4*)&kp[r * DK + c];
            *(float4*)&Vs[r][c] = *(const float4*)&vp[r * DK + c];
        }
        __syncthreads();

        #pragma unroll 2
        for (int j = 0; j < 64; j++) {
            float s0 = 0.f, s1 = 0.f, s2 = 0.f, s3 = 0.f;
            #pragma unroll
            for (int d = 0; d < DK; d += 4) {
                s0 += q[d + 0] * Ks[j][d + 0];
                s1 += q[d + 1] * Ks[j][d + 1];
                s2 += q[d + 2] * Ks[j][d + 2];
                s3 += q[d + 3] * Ks[j][d + 3];
            }
            float s = ((s0 + s1) + (s2 + s3)) * scale;

            if (s > mval) {
                float corr = __expf(mval - s);
                l *= corr;
                #pragma unroll
                for (int d = 0; d < DK; d++) acc[d] *= corr;
                mval = s;
            }
            float p = __expf(s - mval);
            l += p;
            #pragma unroll
            for (int d = 0; d < DK; d++) acc[d] += p * Vs[j][d];
        }
        __syncthreads();
    }

    const float inv = 1.f / l;
    const int b_idx = bh >> 4;
    const int h_idx = bh & 15;
    float* op = Out + ((size_t)b_idx * SEQ + row) * D_MODEL + h_idx * DK;
    #pragma unroll
    for (int i = 0; i < DK / 4; i++) {
        float4 v;
        v.x = acc[i * 4 + 0] * inv;
        v.y = acc[i * 4 + 1] * inv;
        v.z = acc[i * 4 + 2] * inv;
        v.w = acc[i * 4 + 3] * inv;
        *(float4*)&op[i * 4] = v;
    }
}

// ---------------------------------------------------------------------------
extern "C" void kernel_launch(void* const* d_in, const int* in_sizes, int n_in,
                              void* d_out, int out_size)
{
    const float* Q  = (const float*)d_in[0];
    const float* K  = (const float*)d_in[1];
    const float* V  = (const float*)d_in[2];
    const float* Wq = (const float*)d_in[3];
    const float* bq = (const float*)d_in[4];
    const float* Wk = (const float*)d_in[5];
    const float* bk = (const float*)d_in[6];
    const float* Wv = (const float*)d_in[7];
    const float* bv = (const float*)d_in[8];
    const float* Wo = (const float*)d_in[9];
    const float* bo = (const float*)d_in[10];
    float* out = (float*)d_out;

    float *gq, *gk, *gv, *ga;
    cudaGetSymbolAddress((void**)&gq, g_q);
    cudaGetSymbolAddress((void**)&gk, g_k);
    cudaGetSymbolAddress((void**)&gv, g_v);
    cudaGetSymbolAddress((void**)&ga, g_attn);

    dim3 ggrid(D_MODEL / 128, MTOT / 128);   // (8, 32)
    gemm_bias_k<true><<<ggrid, 256>>>(Q, Wq, bq, gq);
    gemm_bias_k<true><<<ggrid, 256>>>(K, Wk, bk, gk);
    gemm_bias_k<true><<<ggrid, 256>>>(V, Wv, bv, gv);

    flash_attn_k<<<BH * (SEQ / 128), 128>>>(gq, gk, gv, ga);

    gemm_bias_k<false><<<ggrid, 256>>>(ga, Wo, bo, out);
}

// round 3
// speedup vs baseline: 3.4705x; 3.4705x over previous
#include <cuda_runtime.h>
#include <stdint.h>
#include <math.h>

#define D_MODEL 1024
#define NHEAD   16
#define DK      64
#define SEQ     2048
#define BATCH   2
#define MTOT    (BATCH * SEQ)          // 4096
#define BH      (BATCH * NHEAD)        // 32

// Scratch (device globals: allocation-free)
__device__ float g_q[MTOT * D_MODEL];     // [BH, S, DK] head layout
__device__ float g_k[MTOT * D_MODEL];
__device__ float g_v[MTOT * D_MODEL];
__device__ float g_attn[MTOT * D_MODEL];  // [B, S, D] plain layout

// ===========================================================================
// Helpers (sm_103 base target: mma.sync + cp.async only, NO tcgen05)
// ===========================================================================
__device__ __forceinline__ uint32_t smem_u32(const void* p) {
    uint32_t a;
    asm("{ .reg .u64 t; cvta.to.shared.u64 t, %1; cvt.u32.u64 %0, t; }"
        : "=r"(a) : "l"(p));
    return a;
}
__device__ __forceinline__ uint32_t f2tf32(float x) {
    uint32_t t;
    asm("cvt.rna.tf32.f32 %0, %1;" : "=r"(t) : "f"(x));
    return t;
}
__device__ __forceinline__ void mma_tf32(float* d, const uint32_t* a,
                                         const uint32_t* b) {
    asm volatile(
        "mma.sync.aligned.m16n8k8.row.col.f32.tf32.tf32.f32 "
        "{%0,%1,%2,%3}, {%4,%5,%6,%7}, {%8,%9}, {%0,%1,%2,%3};"
        : "+f"(d[0]), "+f"(d[1]), "+f"(d[2]), "+f"(d[3])
        : "r"(a[0]), "r"(a[1]), "r"(a[2]), "r"(a[3]), "r"(b[0]), "r"(b[1]));
}
#define CP16(dst, src) \
    asm volatile("cp.async.ca.shared.global [%0], [%1], 16;" :: "r"(dst), "l"(src))
#define CP_COMMIT() asm volatile("cp.async.commit_group;")
#define CP_WAIT0()  asm volatile("cp.async.wait_group 0;")
#define CP_WAIT1()  asm volatile("cp.async.wait_group 1;")

// ===========================================================================
// tf32 tensor-core GEMM: C[4096,1024] = X @ W[K,N] + bias
// 128x128 CTA tile, 8 warps (warp tile 32x64), k-chunk 32, 2-stage cp.async.
// ===========================================================================
#define A_STRIDE 36
#define B_STRIDE 136
#define A_ST (128 * A_STRIDE)          // floats per stage
#define B_ST (32 * B_STRIDE)
#define GSTAGE (A_ST + B_ST)           // 8960 floats
#define GEMM_SMEM (2 * GSTAGE * 4)     // 71680 bytes

template <bool HEAD>
__global__ __launch_bounds__(256)
void gemm_tc(const float* __restrict__ X, const float* __restrict__ W,
             const float* __restrict__ bias, float* __restrict__ C)
{
    extern __shared__ float sm[];
    float* As[2] = { sm, sm + GSTAGE };
    float* Bs[2] = { sm + A_ST, sm + GSTAGE + A_ST };

    const int tid = threadIdx.x;
    const int lane = tid & 31, wid = tid >> 5;
    const int g = lane >> 2, q = lane & 3;
    const int m0 = blockIdx.y * 128, n0 = blockIdx.x * 128;
    const int wm = (wid & 3) * 32, wn = (wid >> 2) * 64;

    float acc[2][8][4];
    #pragma unroll
    for (int mt = 0; mt < 2; mt++)
        #pragma unroll
        for (int nt = 0; nt < 8; nt++)
            #pragma unroll
            for (int i = 0; i < 4; i++) acc[mt][nt][i] = 0.f;

    // stage loader (k-chunk c -> stage st)
    auto load_stage = [&](int c, int st) {
        int k0 = c * 32;
        #pragma unroll
        for (int i = 0; i < 4; i++) {
            int j = tid + i * 256;
            int r = j >> 3, c4 = j & 7;
            CP16(smem_u32(&As[st][r * A_STRIDE + c4 * 4]),
                 &X[(size_t)(m0 + r) * D_MODEL + k0 + c4 * 4]);
        }
        #pragma unroll
        for (int i = 0; i < 4; i++) {
            int j = tid + i * 256;
            int r = j >> 5, c4 = j & 31;
            CP16(smem_u32(&Bs[st][r * B_STRIDE + c4 * 4]),
                 &W[(size_t)(k0 + r) * D_MODEL + n0 + c4 * 4]);
        }
        CP_COMMIT();
    };

    load_stage(0, 0);

    for (int c = 0; c < 32; c++) {
        const int st = c & 1;
        if (c + 1 < 32) { load_stage(c + 1, (c + 1) & 1); CP_WAIT1(); }
        else           { CP_WAIT0(); }
        __syncthreads();

        const float* Ap = As[st];
        const float* Bp = Bs[st];
        #pragma unroll
        for (int ks = 0; ks < 4; ks++) {
            uint32_t af[2][4];
            #pragma unroll
            for (int mt = 0; mt < 2; mt++) {
                int r = wm + mt * 16 + g;
                af[mt][0] = f2tf32(Ap[r * A_STRIDE + ks * 8 + q]);
                af[mt][1] = f2tf32(Ap[(r + 8) * A_STRIDE + ks * 8 + q]);
                af[mt][2] = f2tf32(Ap[r * A_STRIDE + ks * 8 + q + 4]);
                af[mt][3] = f2tf32(Ap[(r + 8) * A_STRIDE + ks * 8 + q + 4]);
            }
            #pragma unroll
            for (int nt = 0; nt < 8; nt++) {
                uint32_t bf[2];
                int col = wn + nt * 8 + g;
                bf[0] = f2tf32(Bp[(ks * 8 + q) * B_STRIDE + col]);
                bf[1] = f2tf32(Bp[(ks * 8 + q + 4) * B_STRIDE + col]);
                mma_tf32(acc[0][nt], af[0], bf);
                mma_tf32(acc[1][nt], af[1], bf);
            }
        }
        __syncthreads();
    }

    // Epilogue: bias + store (C layout: rows g,g+8; cols 2q,2q+1)
    #pragma unroll
    for (int mt = 0; mt < 2; mt++) {
        int m = m0 + wm + mt * 16 + g;
        int b_idx = m >> 11, s_idx = m & 2047;
        #pragma unroll
        for (int nt = 0; nt < 8; nt++) {
            int n = n0 + wn + nt * 8 + 2 * q;
            float bx = bias[n], by = bias[n + 1];
            float2 v0 = { acc[mt][nt][0] + bx, acc[mt][nt][1] + by };
            float2 v1 = { acc[mt][nt][2] + bx, acc[mt][nt][3] + by };
            if (HEAD) {
                int h = n >> 6, d = n & 63;
                float* base = &C[(size_t)(b_idx * NHEAD + h) * (SEQ * DK)];
                *(float2*)&base[(size_t)s_idx * DK + d] = v0;
                *(float2*)&base[(size_t)(s_idx + 8) * DK + d] = v1;
            } else {
                *(float2*)&C[(size_t)m * D_MODEL + n] = v0;
                *(float2*)&C[(size_t)(m + 8) * D_MODEL + n] = v1;
            }
        }
    }
}

// ===========================================================================
// Flash attention, tf32 mma.sync. Block = (bh, 64 q rows), 4 warps x 16 rows.
// ===========================================================================
#define KS_STRIDE 68
#define VS_STRIDE 72
#define PS_STRIDE 68
#define KS_OFF 0
#define VS_OFF (64 * KS_STRIDE)                 // floats
#define PS_OFF (VS_OFF + 64 * VS_STRIDE)
#define FLASH_SMEM ((PS_OFF + 4 * 16 * PS_STRIDE) * 4)   // 53248 bytes

__global__ __launch_bounds__(128)
void flash_tc(const float* __restrict__ Qh, const float* __restrict__ Kh,
              const float* __restrict__ Vh, float* __restrict__ Out)
{
    extern __shared__ float sm[];
    float* Ks = sm + KS_OFF;
    float* Vs = sm + VS_OFF;

    const int tid = threadIdx.x;
    const int lane = tid & 31, w = tid >> 5;
    const int g = lane >> 2, q = lane & 3;
    const int qt = blockIdx.x & 31;      // q-tile (64 rows)
    const int bh = blockIdx.x >> 5;
    const int qbase = qt * 64 + w * 16;

    float* Ps = sm + PS_OFF + w * 16 * PS_STRIDE;

    // Q fragments (pre-scaled by 1/sqrt(64), tf32-converted), register-resident
    uint32_t Qa[8][4];
    {
        const float* qp = Qh + ((size_t)bh * SEQ + qbase) * DK;
        #pragma unroll
        for (int ks = 0; ks < 8; ks++) {
            Qa[ks][0] = f2tf32(qp[g * DK + ks * 8 + q] * 0.125f);
            Qa[ks][1] = f2tf32(qp[(g + 8) * DK + ks * 8 + q] * 0.125f);
            Qa[ks][2] = f2tf32(qp[g * DK + ks * 8 + q + 4] * 0.125f);
            Qa[ks][3] = f2tf32(qp[(g + 8) * DK + ks * 8 + q + 4] * 0.125f);
        }
    }

    float O[8][4];
    #pragma unroll
    for (int nt = 0; nt < 8; nt++)
        #pragma unroll
        for (int i = 0; i < 4; i++) O[nt][i] = 0.f;
    float m0 = -1e30f, m1 = -1e30f, l0 = 0.f, l1 = 0.f;

    for (int kt = 0; kt < SEQ / 64; kt++) {
        // Load K/V tile (64 x 64) via cp.async
        const float* kp = Kh + ((size_t)bh * SEQ + kt * 64) * DK;
        const float* vp = Vh + ((size_t)bh * SEQ + kt * 64) * DK;
        #pragma unroll
        for (int i = 0; i < 8; i++) {
            int j = tid + i * 128;
            int r = j >> 4, c4 = j & 15;
            CP16(smem_u32(&Ks[r * KS_STRIDE + c4 * 4]), &kp[r * DK + c4 * 4]);
        }
        #pragma unroll
        for (int i = 0; i < 8; i++) {
            int j = tid + i * 128;
            int r = j >> 4, c4 = j & 15;
            CP16(smem_u32(&Vs[r * VS_STRIDE + c4 * 4]), &vp[r * DK + c4 * 4]);
        }
        CP_COMMIT();
        CP_WAIT0();
        __syncthreads();

        // S = Q @ K^T  (already scaled via Q)
        float S[8][4];
        #pragma unroll
        for (int nt = 0; nt < 8; nt++) {
            #pragma unroll
            for (int i = 0; i < 4; i++) S[nt][i] = 0.f;
            #pragma unroll
            for (int ks = 0; ks < 8; ks++) {
                uint32_t bf[2];
                bf[0] = f2tf32(Ks[(nt * 8 + g) * KS_STRIDE + ks * 8 + q]);
                bf[1] = f2tf32(Ks[(nt * 8 + g) * KS_STRIDE + ks * 8 + q + 4]);
                mma_tf32(S[nt], Qa[ks], bf);
            }
        }

        // Online softmax (rows: g -> m0/l0, g+8 -> m1/l1)
        float mx0 = -1e30f, mx1 = -1e30f;
        #pragma unroll
        for (int nt = 0; nt < 8; nt++) {
            mx0 = fmaxf(mx0, fmaxf(S[nt][0], S[nt][1]));
            mx1 = fmaxf(mx1, fmaxf(S[nt][2], S[nt][3]));
        }
        mx0 = fmaxf(mx0, __shfl_xor_sync(0xFFFFFFFF, mx0, 1));
        mx0 = fmaxf(mx0, __shfl_xor_sync(0xFFFFFFFF, mx0, 2));
        mx1 = fmaxf(mx1, __shfl_xor_sync(0xFFFFFFFF, mx1, 1));
        mx1 = fmaxf(mx1, __shfl_xor_sync(0xFFFFFFFF, mx1, 2));

        float mn0 = fmaxf(m0, mx0), mn1 = fmaxf(m1, mx1);
        float c0 = __expf(m0 - mn0), c1 = __expf(m1 - mn1);
        m0 = mn0; m1 = mn1;

        float s0 = 0.f, s1 = 0.f;
        #pragma unroll
        for (int nt = 0; nt < 8; nt++) {
            float p0 = __expf(S[nt][0] - mn0);
            float p1 = __expf(S[nt][1] - mn0);
            float p2 = __expf(S[nt][2] - mn1);
            float p3 = __expf(S[nt][3] - mn1);
            s0 += p0 + p1; s1 += p2 + p3;
            *(float2*)&Ps[g * PS_STRIDE + nt * 8 + 2 * q] = make_float2(p0, p1);
            *(float2*)&Ps[(g + 8) * PS_STRIDE + nt * 8 + 2 * q] = make_float2(p2, p3);
        }
        s0 += __shfl_xor_sync(0xFFFFFFFF, s0, 1);
        s0 += __shfl_xor_sync(0xFFFFFFFF, s0, 2);
        s1 += __shfl_xor_sync(0xFFFFFFFF, s1, 1);
        s1 += __shfl_xor_sync(0xFFFFFFFF, s1, 2);
        l0 = l0 * c0 + s0;
        l1 = l1 * c1 + s1;

        #pragma unroll
        for (int nt = 0; nt < 8; nt++) {
            O[nt][0] *= c0; O[nt][1] *= c0;
            O[nt][2] *= c1; O[nt][3] *= c1;
        }
        __syncwarp();

        // O += P @ V
        #pragma unroll
        for (int ks = 0; ks < 8; ks++) {
            uint32_t pa[4];
            pa[0] = f2tf32(Ps[g * PS_STRIDE + ks * 8 + q]);
            pa[1] = f2tf32(Ps[(g + 8) * PS_STRIDE + ks * 8 + q]);
            pa[2] = f2tf32(Ps[g * PS_STRIDE + ks * 8 + q + 4]);
            pa[3] = f2tf32(Ps[(g + 8) * PS_STRIDE + ks * 8 + q + 4]);
            #pragma unroll
            for (int nt = 0; nt < 8; nt++) {
                uint32_t bf[2];
                bf[0] = f2tf32(Vs[(ks * 8 + q) * VS_STRIDE + nt * 8 + g]);
                bf[1] = f2tf32(Vs[(ks * 8 + q + 4) * VS_STRIDE + nt * 8 + g]);
                mma_tf32(O[nt], pa, bf);
            }
        }
        __syncthreads();
    }

    // Normalize + store to [B, S, D]
    const float i0 = 1.f / l0, i1 = 1.f / l1;
    const int b_idx = bh >> 4, h_idx = bh & 15;
    float* op = Out + ((size_t)b_idx * SEQ) * D_MODEL + h_idx * DK;
    #pragma unroll
    for (int nt = 0; nt < 8; nt++) {
        int d = nt * 8 + 2 * q;
        *(float2*)&op[(size_t)(qbase + g) * D_MODEL + d] =
            make_float2(O[nt][0] * i0, O[nt][1] * i0);
        *(float2*)&op[(size_t)(qbase + g + 8) * D_MODEL + d] =
            make_float2(O[nt][2] * i1, O[nt][3] * i1);
    }
}

// ===========================================================================
extern "C" void kernel_launch(void* const* d_in, const int* in_sizes, int n_in,
                              void* d_out, int out_size)
{
    const float* Q  = (const float*)d_in[0];
    const float* K  = (const float*)d_in[1];
    const float* V  = (const float*)d_in[2];
    const float* Wq = (const float*)d_in[3];
    const float* bq = (const float*)d_in[4];
    const float* Wk = (const float*)d_in[5];
    const float* bk = (const float*)d_in[6];
    const float* Wv = (const float*)d_in[7];
    const float* bv = (const float*)d_in[8];
    const float* Wo = (const float*)d_in[9];
    const float* bo = (const float*)d_in[10];
    float* out = (float*)d_out;

    float *gq, *gk, *gv, *ga;
    cudaGetSymbolAddress((void**)&gq, g_q);
    cudaGetSymbolAddress((void**)&gk, g_k);
    cudaGetSymbolAddress((void**)&gv, g_v);
    cudaGetSymbolAddress((void**)&ga, g_attn);

    cudaFuncSetAttribute(gemm_tc<true>,
                         cudaFuncAttributeMaxDynamicSharedMemorySize, GEMM_SMEM);
    cudaFuncSetAttribute(gemm_tc<false>,
                         cudaFuncAttributeMaxDynamicSharedMemorySize, GEMM_SMEM);
    cudaFuncSetAttribute(flash_tc,
                         cudaFuncAttributeMaxDynamicSharedMemorySize, FLASH_SMEM);

    dim3 ggrid(D_MODEL / 128, MTOT / 128);   // (8, 32)
    gemm_tc<true><<<ggrid, 256, GEMM_SMEM>>>(Q, Wq, bq, gq);
    gemm_tc<true><<<ggrid, 256, GEMM_SMEM>>>(K, Wk, bk, gk);
    gemm_tc<true><<<ggrid, 256, GEMM_SMEM>>>(V, Wv, bv, gv);

    flash_tc<<<BH * (SEQ / 64), 128, FLASH_SMEM>>>(gq, gk, gv, ga);

    gemm_tc<false><<<ggrid, 256, GEMM_SMEM>>>(ga, Wo, bo, out);
}

// round 4
// speedup vs baseline: 6.6133x; 1.9056x over previous
#include <cuda_runtime.h>
#include <cuda_fp16.h>
#include <stdint.h>

#define D_MODEL 1024
#define NHEAD   16
#define DK      64
#define SEQ     2048
#define BATCH   2
#define MTOT    (BATCH * SEQ)          // 4096
#define BH      (BATCH * NHEAD)        // 32

// --------------------------- device scratch (halfs) ------------------------
__device__ __half h_qi[MTOT * D_MODEL];   // converted inputs
__device__ __half h_ki[MTOT * D_MODEL];
__device__ __half h_vi[MTOT * D_MODEL];
__device__ __half h_w[4 * D_MODEL * D_MODEL];  // converted weights [K,N]
__device__ __half h_q[MTOT * D_MODEL];    // projected, head layout, pre-scaled
__device__ __half h_k[MTOT * D_MODEL];
__device__ __half h_v[MTOT * D_MODEL];
__device__ __half h_a[MTOT * D_MODEL];    // attention out [B,S,D]

// ------------------------------- helpers -----------------------------------
__device__ __forceinline__ uint32_t smem_u32(const void* p) {
    uint32_t a;
    asm("{ .reg .u64 t; cvta.to.shared.u64 t, %1; cvt.u32.u64 %0, t; }"
        : "=r"(a) : "l"(p));
    return a;
}
__device__ __forceinline__ void mma_f16(float* d, const uint32_t* a,
                                        const uint32_t* b) {
    asm volatile(
        "mma.sync.aligned.m16n8k16.row.col.f32.f16.f16.f32 "
        "{%0,%1,%2,%3}, {%4,%5,%6,%7}, {%8,%9}, {%0,%1,%2,%3};"
        : "+f"(d[0]), "+f"(d[1]), "+f"(d[2]), "+f"(d[3])
        : "r"(a[0]), "r"(a[1]), "r"(a[2]), "r"(a[3]), "r"(b[0]), "r"(b[1]));
}
__device__ __forceinline__ void ldsm_x4_t(uint32_t& d0, uint32_t& d1,
                                          uint32_t& d2, uint32_t& d3,
                                          uint32_t addr) {
    asm volatile("ldmatrix.sync.aligned.m8n8.x4.trans.shared.b16 "
                 "{%0,%1,%2,%3}, [%4];"
                 : "=r"(d0), "=r"(d1), "=r"(d2), "=r"(d3) : "r"(addr));
}
#define CP16(dst, src) \
    asm volatile("cp.async.ca.shared.global [%0], [%1], 16;" :: "r"(dst), "l"(src))
#define CP_COMMIT() asm volatile("cp.async.commit_group;")
#define CP_WAIT0()  asm volatile("cp.async.wait_group 0;")
#define CP_WAIT1()  asm volatile("cp.async.wait_group 1;")

// --------------------------- f32 -> f16 convert ----------------------------
__global__ __launch_bounds__(256)
void f2h(const float4* __restrict__ src, uint2* __restrict__ dst, int n4)
{
    int i = blockIdx.x * blockDim.x + threadIdx.x;
    if (i < n4) {
        float4 v = src[i];
        __half2 a = __floats2half2_rn(v.x, v.y);
        __half2 b = __floats2half2_rn(v.z, v.w);
        uint2 o;
        o.x = *(uint32_t*)&a;
        o.y = *(uint32_t*)&b;
        dst[i] = o;
    }
}

// ===========================================================================
// fp16 tensor-core GEMM: C[4096,1024] = X @ W[K,N] (+bias, opt. head/scale)
// 128x128 CTA tile, 8 warps (32x64 warp tile), k-chunk 32, 3-stage cp.async.
// MODE 0: f32 plain out; MODE 1: half head-scatter; MODE 2: half head *0.125
// ===========================================================================
#define AH_STRIDE 40
#define BHS 136
#define A_STAGE (128 * AH_STRIDE)       // 5120 halfs
#define B_STAGE (32 * BHS)              // 4352 halfs
#define G_STAGE (A_STAGE + B_STAGE)     // 9472 halfs
#define G_SMEM (3 * G_STAGE * 2)        // 56832 bytes

template <int MODE>
__global__ __launch_bounds__(256)
void gemm_h(const __half* __restrict__ X, const __half* __restrict__ W,
            const float* __restrict__ bias, void* __restrict__ Cv)
{
    extern __shared__ __half sh[];
    const int tid = threadIdx.x;
    const int lane = tid & 31, wid = tid >> 5;
    const int g = lane >> 2, q = lane & 3;
    const int m0 = blockIdx.y * 128, n0 = blockIdx.x * 128;
    const int wm = (wid & 3) * 32, wn = (wid >> 2) * 64;

    float acc[2][8][4];
    #pragma unroll
    for (int mt = 0; mt < 2; mt++)
        #pragma unroll
        for (int nt = 0; nt < 8; nt++)
            #pragma unroll
            for (int i = 0; i < 4; i++) acc[mt][nt][i] = 0.f;

    auto load_stage = [&](int c, int st) {
        __half* As = sh + st * G_STAGE;
        __half* Bs = As + A_STAGE;
        int k0 = c * 32;
        #pragma unroll
        for (int i = 0; i < 2; i++) {
            int j = tid + i * 256;
            int r = j >> 2, c8 = j & 3;
            CP16(smem_u32(&As[r * AH_STRIDE + c8 * 8]),
                 &X[(size_t)(m0 + r) * D_MODEL + k0 + c8 * 8]);
        }
        #pragma unroll
        for (int i = 0; i < 2; i++) {
            int j = tid + i * 256;
            int r = j >> 4, c8 = j & 15;
            CP16(smem_u32(&Bs[r * BHS + c8 * 8]),
                 &W[(size_t)(k0 + r) * D_MODEL + n0 + c8 * 8]);
        }
        CP_COMMIT();
    };

    load_stage(0, 0);
    load_stage(1, 1);

    for (int c = 0; c < 32; c++) {
        const int st = c % 3;
        if (c < 31) { CP_WAIT1(); } else { CP_WAIT0(); }
        __syncthreads();
        if (c + 2 < 32) load_stage(c + 2, (c + 2) % 3);

        const __half* As = sh + st * G_STAGE;
        const __half* Bs = As + A_STAGE;
        #pragma unroll
        for (int ks = 0; ks < 2; ks++) {
            uint32_t af[2][4];
            #pragma unroll
            for (int mt = 0; mt < 2; mt++) {
                int r = wm + mt * 16 + g;
                af[mt][0] = *(const uint32_t*)&As[r * AH_STRIDE + ks * 16 + 2 * q];
                af[mt][1] = *(const uint32_t*)&As[(r + 8) * AH_STRIDE + ks * 16 + 2 * q];
                af[mt][2] = *(const uint32_t*)&As[r * AH_STRIDE + ks * 16 + 2 * q + 8];
                af[mt][3] = *(const uint32_t*)&As[(r + 8) * AH_STRIDE + ks * 16 + 2 * q + 8];
            }
            #pragma unroll
            for (int tp = 0; tp < 4; tp++) {
                uint32_t b0, b1, b2, b3;
                int row = ks * 16 + (lane & 15);
                int col = wn + tp * 16 + ((lane >> 4) & 1) * 8;
                ldsm_x4_t(b0, b1, b2, b3, smem_u32(&Bs[row * BHS + col]));
                uint32_t bb0[2] = { b0, b1 }, bb1[2] = { b2, b3 };
                mma_f16(acc[0][2 * tp], af[0], bb0);
                mma_f16(acc[1][2 * tp], af[1], bb0);
                mma_f16(acc[0][2 * tp + 1], af[0], bb1);
                mma_f16(acc[1][2 * tp + 1], af[1], bb1);
            }
        }
    }

    // Epilogue
    #pragma unroll
    for (int mt = 0; mt < 2; mt++) {
        int m = m0 + wm + mt * 16 + g;
        int b_idx = m >> 11, s_idx = m & 2047;
        #pragma unroll
        for (int nt = 0; nt < 8; nt++) {
            int n = n0 + wn + nt * 8 + 2 * q;
            float bx = bias[n], by = bias[n + 1];
            float v00 = acc[mt][nt][0] + bx, v01 = acc[mt][nt][1] + by;
            float v10 = acc[mt][nt][2] + bx, v11 = acc[mt][nt][3] + by;
            if (MODE == 2) { v00 *= 0.125f; v01 *= 0.125f; v10 *= 0.125f; v11 *= 0.125f; }
            if (MODE >= 1) {
                int h = n >> 6, d = n & 63;
                __half* base = (__half*)Cv + (size_t)(b_idx * NHEAD + h) * (SEQ * DK);
                __half2 h0 = __floats2half2_rn(v00, v01);
                __half2 h1 = __floats2half2_rn(v10, v11);
                *(uint32_t*)&base[(size_t)s_idx * DK + d] = *(uint32_t*)&h0;
                *(uint32_t*)&base[(size_t)(s_idx + 8) * DK + d] = *(uint32_t*)&h1;
            } else {
                float* Cf = (float*)Cv;
                *(float2*)&Cf[(size_t)m * D_MODEL + n] = make_float2(v00, v01);
                *(float2*)&Cf[(size_t)(m + 8) * D_MODEL + n] = make_float2(v10, v11);
            }
        }
    }
}

// ===========================================================================
// Flash attention, fp16 mma. Block = (bh, 64 q rows), 4 warps x 16 rows.
// 2-stage cp.async K/V double buffer, fp32 softmax, half output.
// ===========================================================================
#define KVS 72
#define KV_TILE (64 * KVS)               // 4608 halfs (one of K or V)
#define F_STAGE (2 * KV_TILE)            // 9216 halfs (K+V)
#define PS_BASE (2 * F_STAGE)            // 18432 halfs
#define F_SMEM ((PS_BASE + 4 * 16 * KVS) * 2)   // 46080 bytes

__global__ __launch_bounds__(128)
void flash_h(const __half* __restrict__ Qh, const __half* __restrict__ Kh,
             const __half* __restrict__ Vh, __half* __restrict__ Out)
{
    extern __shared__ __half sh[];
    const int tid = threadIdx.x;
    const int lane = tid & 31, w = tid >> 5;
    const int g = lane >> 2, q = lane & 3;
    const int qt = blockIdx.x & 31;
    const int bh = blockIdx.x >> 5;
    const int qbase = qt * 64 + w * 16;

    __half* Ps = sh + PS_BASE + w * 16 * KVS;

    auto load_kv = [&](int kt, int st) {
        __half* Ks = sh + st * F_STAGE;
        __half* Vs = Ks + KV_TILE;
        const __half* kp = Kh + ((size_t)bh * SEQ + kt * 64) * DK;
        const __half* vp = Vh + ((size_t)bh * SEQ + kt * 64) * DK;
        #pragma unroll
        for (int i = 0; i < 4; i++) {
            int j = tid + i * 128;
            int r = j >> 3, c8 = j & 7;
            CP16(smem_u32(&Ks[r * KVS + c8 * 8]), &kp[r * DK + c8 * 8]);
        }
        #pragma unroll
        for (int i = 0; i < 4; i++) {
            int j = tid + i * 128;
            int r = j >> 3, c8 = j & 7;
            CP16(smem_u32(&Vs[r * KVS + c8 * 8]), &vp[r * DK + c8 * 8]);
        }
        CP_COMMIT();
    };

    // Q fragments (already scaled at projection), register-resident
    uint32_t Qa[4][4];
    {
        const __half* qp = Qh + ((size_t)bh * SEQ + qbase) * DK;
        #pragma unroll
        for (int ks = 0; ks < 4; ks++) {
            Qa[ks][0] = *(const uint32_t*)&qp[g * DK + ks * 16 + 2 * q];
            Qa[ks][1] = *(const uint32_t*)&qp[(g + 8) * DK + ks * 16 + 2 * q];
            Qa[ks][2] = *(const uint32_t*)&qp[g * DK + ks * 16 + 2 * q + 8];
            Qa[ks][3] = *(const uint32_t*)&qp[(g + 8) * DK + ks * 16 + 2 * q + 8];
        }
    }

    float O[8][4];
    #pragma unroll
    for (int nt = 0; nt < 8; nt++)
        #pragma unroll
        for (int i = 0; i < 4; i++) O[nt][i] = 0.f;
    float m0 = -1e30f, m1 = -1e30f, l0 = 0.f, l1 = 0.f;

    load_kv(0, 0);

    for (int kt = 0; kt < SEQ / 64; kt++) {
        CP_WAIT0();
        __syncthreads();
        if (kt + 1 < SEQ / 64) load_kv(kt + 1, (kt + 1) & 1);

        const __half* Ks = sh + (kt & 1) * F_STAGE;
        const __half* Vs = Ks + KV_TILE;

        // S = Qs @ K^T
        float S[8][4];
        #pragma unroll
        for (int nt = 0; nt < 8; nt++) {
            #pragma unroll
            for (int i = 0; i < 4; i++) S[nt][i] = 0.f;
            #pragma unroll
            for (int ks = 0; ks < 4; ks++) {
                uint32_t bb[2];
                bb[0] = *(const uint32_t*)&Ks[(nt * 8 + g) * KVS + ks * 16 + 2 * q];
                bb[1] = *(const uint32_t*)&Ks[(nt * 8 + g) * KVS + ks * 16 + 2 * q + 8];
                mma_f16(S[nt], Qa[ks], bb);
            }
        }

        // Online softmax
        float mx0 = -1e30f, mx1 = -1e30f;
        #pragma unroll
        for (int nt = 0; nt < 8; nt++) {
            mx0 = fmaxf(mx0, fmaxf(S[nt][0], S[nt][1]));
            mx1 = fmaxf(mx1, fmaxf(S[nt][2], S[nt][3]));
        }
        mx0 = fmaxf(mx0, __shfl_xor_sync(0xFFFFFFFF, mx0, 1));
        mx0 = fmaxf(mx0, __shfl_xor_sync(0xFFFFFFFF, mx0, 2));
        mx1 = fmaxf(mx1, __shfl_xor_sync(0xFFFFFFFF, mx1, 1));
        mx1 = fmaxf(mx1, __shfl_xor_sync(0xFFFFFFFF, mx1, 2));

        float mn0 = fmaxf(m0, mx0), mn1 = fmaxf(m1, mx1);
        float c0 = __expf(m0 - mn0), c1 = __expf(m1 - mn1);
        m0 = mn0; m1 = mn1;

        float s0 = 0.f, s1 = 0.f;
        #pragma unroll
        for (int nt = 0; nt < 8; nt++) {
            float p0 = __expf(S[nt][0] - mn0);
            float p1 = __expf(S[nt][1] - mn0);
            float p2 = __expf(S[nt][2] - mn1);
            float p3 = __expf(S[nt][3] - mn1);
            s0 += p0 + p1; s1 += p2 + p3;
            __half2 hp0 = __floats2half2_rn(p0, p1);
            __half2 hp1 = __floats2half2_rn(p2, p3);
            *(uint32_t*)&Ps[g * KVS + nt * 8 + 2 * q] = *(uint32_t*)&hp0;
            *(uint32_t*)&Ps[(g + 8) * KVS + nt * 8 + 2 * q] = *(uint32_t*)&hp1;
        }
        s0 += __shfl_xor_sync(0xFFFFFFFF, s0, 1);
        s0 += __shfl_xor_sync(0xFFFFFFFF, s0, 2);
        s1 += __shfl_xor_sync(0xFFFFFFFF, s1, 1);
        s1 += __shfl_xor_sync(0xFFFFFFFF, s1, 2);
        l0 = l0 * c0 + s0;
        l1 = l1 * c1 + s1;

        #pragma unroll
        for (int nt = 0; nt < 8; nt++) {
            O[nt][0] *= c0; O[nt][1] *= c0;
            O[nt][2] *= c1; O[nt][3] *= c1;
        }
        __syncwarp();

        // O += P @ V  (V B-frags via ldmatrix.trans from [key][dk] smem)
        #pragma unroll
        for (int ks = 0; ks < 4; ks++) {
            uint32_t pa[4];
            pa[0] = *(const uint32_t*)&Ps[g * KVS + ks * 16 + 2 * q];
            pa[1] = *(const uint32_t*)&Ps[(g + 8) * KVS + ks * 16 + 2 * q];
            pa[2] = *(const uint32_t*)&Ps[g * KVS + ks * 16 + 2 * q + 8];
            pa[3] = *(const uint32_t*)&Ps[(g + 8) * KVS + ks * 16 + 2 * q + 8];
            #pragma unroll
            for (int tp = 0; tp < 4; tp++) {
                uint32_t b0, b1, b2, b3;
                int row = ks * 16 + (lane & 15);
                int col = tp * 16 + ((lane >> 4) & 1) * 8;
                ldsm_x4_t(b0, b1, b2, b3, smem_u32(&Vs[row * KVS + col]));
                uint32_t bb0[2] = { b0, b1 }, bb1[2] = { b2, b3 };
                mma_f16(O[2 * tp], pa, bb0);
                mma_f16(O[2 * tp + 1], pa, bb1);
            }
        }
    }

    // Normalize + store half to [B, S, D]
    const float i0 = 1.f / l0, i1 = 1.f / l1;
    const int b_idx = bh >> 4, h_idx = bh & 15;
    __half* op = Out + ((size_t)b_idx * SEQ) * D_MODEL + h_idx * DK;
    #pragma unroll
    for (int nt = 0; nt < 8; nt++) {
        int d = nt * 8 + 2 * q;
        __half2 h0 = __floats2half2_rn(O[nt][0] * i0, O[nt][1] * i0);
        __half2 h1 = __floats2half2_rn(O[nt][2] * i1, O[nt][3] * i1);
        *(uint32_t*)&op[(size_t)(qbase + g) * D_MODEL + d] = *(uint32_t*)&h0;
        *(uint32_t*)&op[(size_t)(qbase + g + 8) * D_MODEL + d] = *(uint32_t*)&h1;
    }
}

// ===========================================================================
extern "C" void kernel_launch(void* const* d_in, const int* in_sizes, int n_in,
                              void* d_out, int out_size)
{
    const float* Q  = (const float*)d_in[0];
    const float* K  = (const float*)d_in[1];
    const float* V  = (const float*)d_in[2];
    const float* Wq = (const float*)d_in[3];
    const float* bq = (const float*)d_in[4];
    const float* Wk = (const float*)d_in[5];
    const float* bk = (const float*)d_in[6];
    const float* Wv = (const float*)d_in[7];
    const float* bv = (const float*)d_in[8];
    const float* Wo = (const float*)d_in[9];
    const float* bo = (const float*)d_in[10];
    float* out = (float*)d_out;

    __half *qi, *ki, *vi, *wh, *qh, *kh, *vh, *ah;
    cudaGetSymbolAddress((void**)&qi, h_qi);
    cudaGetSymbolAddress((void**)&ki, h_ki);
    cudaGetSymbolAddress((void**)&vi, h_vi);
    cudaGetSymbolAddress((void**)&wh, h_w);
    cudaGetSymbolAddress((void**)&qh, h_q);
    cudaGetSymbolAddress((void**)&kh, h_k);
    cudaGetSymbolAddress((void**)&vh, h_v);
    cudaGetSymbolAddress((void**)&ah, h_a);

    cudaFuncSetAttribute(gemm_h<0>, cudaFuncAttributeMaxDynamicSharedMemorySize, G_SMEM);
    cudaFuncSetAttribute(gemm_h<1>, cudaFuncAttributeMaxDynamicSharedMemorySize, G_SMEM);
    cudaFuncSetAttribute(gemm_h<2>, cudaFuncAttributeMaxDynamicSharedMemorySize, G_SMEM);
    cudaFuncSetAttribute(flash_h,   cudaFuncAttributeMaxDynamicSharedMemorySize, F_SMEM);

    const int NI4 = MTOT * D_MODEL / 4;          // 1M float4s
    const int NW4 = D_MODEL * D_MODEL / 4;       // 256K float4s
    const size_t WSZ = (size_t)D_MODEL * D_MODEL;

    f2h<<<(NI4 + 255) / 256, 256>>>((const float4*)Q, (uint2*)qi, NI4);
    f2h<<<(NI4 + 255) / 256, 256>>>((const float4*)K, (uint2*)ki, NI4);
    f2h<<<(NI4 + 255) / 256, 256>>>((const float4*)V, (uint2*)vi, NI4);
    f2h<<<(NW4 + 255) / 256, 256>>>((const float4*)Wq, (uint2*)(wh + 0 * WSZ), NW4);
    f2h<<<(NW4 + 255) / 256, 256>>>((const float4*)Wk, (uint2*)(wh + 1 * WSZ), NW4);
    f2h<<<(NW4 + 255) / 256, 256>>>((const float4*)Wv, (uint2*)(wh + 2 * WSZ), NW4);
    f2h<<<(NW4 + 255) / 256, 256>>>((const float4*)Wo, (uint2*)(wh + 3 * WSZ), NW4);

    dim3 ggrid(D_MODEL / 128, MTOT / 128);   // (8, 32)
    gemm_h<2><<<ggrid, 256, G_SMEM>>>(qi, wh + 0 * WSZ, bq, qh);  // Q, *0.125
    gemm_h<1><<<ggrid, 256, G_SMEM>>>(ki, wh + 1 * WSZ, bk, kh);
    gemm_h<1><<<ggrid, 256, G_SMEM>>>(vi, wh + 2 * WSZ, bv, vh);

    flash_h<<<BH * (SEQ / 64), 128, F_SMEM>>>(qh, kh, vh, ah);

    gemm_h<0><<<ggrid, 256, G_SMEM>>>(ah, wh + 3 * WSZ, bo, out);
}

// round 5
// speedup vs baseline: 7.3863x; 1.1169x over previous
#include <cuda_runtime.h>
#include <cuda_fp16.h>
#include <stdint.h>

#define D_MODEL 1024
#define NHEAD   16
#define DK      64
#define SEQ     2048
#define BATCH   2
#define MTOT    (BATCH * SEQ)          // 4096
#define BH      (BATCH * NHEAD)        // 32

// --------------------------- device scratch (halfs) ------------------------
__device__ __half h_qi[MTOT * D_MODEL];
__device__ __half h_ki[MTOT * D_MODEL];
__device__ __half h_vi[MTOT * D_MODEL];
__device__ __half h_w[4 * D_MODEL * D_MODEL];
__device__ __half h_q[MTOT * D_MODEL];    // projected, head layout, pre-scaled
__device__ __half h_k[MTOT * D_MODEL];
__device__ __half h_v[MTOT * D_MODEL];
__device__ __half h_a[MTOT * D_MODEL];    // attention out [B,S,D]

// ------------------------------- helpers -----------------------------------
__device__ __forceinline__ uint32_t smem_u32(const void* p) {
    uint32_t a;
    asm("{ .reg .u64 t; cvta.to.shared.u64 t, %1; cvt.u32.u64 %0, t; }"
        : "=r"(a) : "l"(p));
    return a;
}
__device__ __forceinline__ void mma_f16(float* d, const uint32_t* a,
                                        const uint32_t* b) {
    asm volatile(
        "mma.sync.aligned.m16n8k16.row.col.f32.f16.f16.f32 "
        "{%0,%1,%2,%3}, {%4,%5,%6,%7}, {%8,%9}, {%0,%1,%2,%3};"
        : "+f"(d[0]), "+f"(d[1]), "+f"(d[2]), "+f"(d[3])
        : "r"(a[0]), "r"(a[1]), "r"(a[2]), "r"(a[3]), "r"(b[0]), "r"(b[1]));
}
__device__ __forceinline__ void ldsm_x4_t(uint32_t& d0, uint32_t& d1,
                                          uint32_t& d2, uint32_t& d3,
                                          uint32_t addr) {
    asm volatile("ldmatrix.sync.aligned.m8n8.x4.trans.shared.b16 "
                 "{%0,%1,%2,%3}, [%4];"
                 : "=r"(d0), "=r"(d1), "=r"(d2), "=r"(d3) : "r"(addr));
}
#define CP16(dst, src) \
    asm volatile("cp.async.ca.shared.global [%0], [%1], 16;" :: "r"(dst), "l"(src))
#define CP_COMMIT() asm volatile("cp.async.commit_group;")
#define CP_WAIT0()  asm volatile("cp.async.wait_group 0;")
#define CP_WAIT1()  asm volatile("cp.async.wait_group 1;")

// ------------------- fused f32 -> f16 convert (one launch) -----------------
struct CvtArgs {
    const float4* src[7];
    uint2* dst[7];
    int n4[7];
};
__global__ __launch_bounds__(256)
void f2h_all(CvtArgs args)
{
    int seg = blockIdx.y;
    const float4* src = args.src[seg];
    uint2* dst = args.dst[seg];
    int n4 = args.n4[seg];
    for (int i = blockIdx.x * blockDim.x + threadIdx.x; i < n4;
         i += gridDim.x * blockDim.x) {
        float4 v = src[i];
        __half2 a = __floats2half2_rn(v.x, v.y);
        __half2 b = __floats2half2_rn(v.z, v.w);
        uint2 o;
        o.x = *(uint32_t*)&a;
        o.y = *(uint32_t*)&b;
        dst[i] = o;
    }
}

// ===========================================================================
// fp16 tensor-core GEMM: C[4096,1024] = X @ W[K,N] (+bias)
// 128x128 CTA tile, 8 warps (32x64 warp tile), k-chunk 32, 3-stage cp.async.
// MODE 0: f32 plain out; MODE 1: half head-scatter; MODE 2: half head *0.125
// ===========================================================================
#define AH_STRIDE 40
#define BHS 136
#define A_STAGE (128 * AH_STRIDE)
#define B_STAGE (32 * BHS)
#define G_STAGE (A_STAGE + B_STAGE)
#define G_SMEM (3 * G_STAGE * 2)        // 56832 bytes

template <int MODE>
__global__ __launch_bounds__(256, 2)
void gemm_h(const __half* __restrict__ X, const __half* __restrict__ W,
            const float* __restrict__ bias, void* __restrict__ Cv)
{
    extern __shared__ __half sh[];
    const int tid = threadIdx.x;
    const int lane = tid & 31, wid = tid >> 5;
    const int g = lane >> 2, q = lane & 3;
    const int m0 = blockIdx.y * 128, n0 = blockIdx.x * 128;
    const int wm = (wid & 3) * 32, wn = (wid >> 2) * 64;

    float acc[2][8][4];
    #pragma unroll
    for (int mt = 0; mt < 2; mt++)
        #pragma unroll
        for (int nt = 0; nt < 8; nt++)
            #pragma unroll
            for (int i = 0; i < 4; i++) acc[mt][nt][i] = 0.f;

    auto load_stage = [&](int c, int st) {
        __half* As = sh + st * G_STAGE;
        __half* Bs = As + A_STAGE;
        int k0 = c * 32;
        #pragma unroll
        for (int i = 0; i < 2; i++) {
            int j = tid + i * 256;
            int r = j >> 2, c8 = j & 3;
            CP16(smem_u32(&As[r * AH_STRIDE + c8 * 8]),
                 &X[(size_t)(m0 + r) * D_MODEL + k0 + c8 * 8]);
        }
        #pragma unroll
        for (int i = 0; i < 2; i++) {
            int j = tid + i * 256;
            int r = j >> 4, c8 = j & 15;
            CP16(smem_u32(&Bs[r * BHS + c8 * 8]),
                 &W[(size_t)(k0 + r) * D_MODEL + n0 + c8 * 8]);
        }
        CP_COMMIT();
    };

    load_stage(0, 0);
    load_stage(1, 1);

    for (int c = 0; c < 32; c++) {
        const int st = c % 3;
        if (c < 31) { CP_WAIT1(); } else { CP_WAIT0(); }
        __syncthreads();
        if (c + 2 < 32) load_stage(c + 2, (c + 2) % 3);

        const __half* As = sh + st * G_STAGE;
        const __half* Bs = As + A_STAGE;
        #pragma unroll
        for (int ks = 0; ks < 2; ks++) {
            uint32_t af[2][4];
            #pragma unroll
            for (int mt = 0; mt < 2; mt++) {
                int r = wm + mt * 16 + g;
                af[mt][0] = *(const uint32_t*)&As[r * AH_STRIDE + ks * 16 + 2 * q];
                af[mt][1] = *(const uint32_t*)&As[(r + 8) * AH_STRIDE + ks * 16 + 2 * q];
                af[mt][2] = *(const uint32_t*)&As[r * AH_STRIDE + ks * 16 + 2 * q + 8];
                af[mt][3] = *(const uint32_t*)&As[(r + 8) * AH_STRIDE + ks * 16 + 2 * q + 8];
            }
            #pragma unroll
            for (int tp = 0; tp < 4; tp++) {
                uint32_t b0, b1, b2, b3;
                int row = ks * 16 + (lane & 15);
                int col = wn + tp * 16 + ((lane >> 4) & 1) * 8;
                ldsm_x4_t(b0, b1, b2, b3, smem_u32(&Bs[row * BHS + col]));
                uint32_t bb0[2] = { b0, b1 }, bb1[2] = { b2, b3 };
                mma_f16(acc[0][2 * tp], af[0], bb0);
                mma_f16(acc[1][2 * tp], af[1], bb0);
                mma_f16(acc[0][2 * tp + 1], af[0], bb1);
                mma_f16(acc[1][2 * tp + 1], af[1], bb1);
            }
        }
    }

    // Epilogue
    #pragma unroll
    for (int mt = 0; mt < 2; mt++) {
        int m = m0 + wm + mt * 16 + g;
        int b_idx = m >> 11, s_idx = m & 2047;
        #pragma unroll
        for (int nt = 0; nt < 8; nt++) {
            int n = n0 + wn + nt * 8 + 2 * q;
            float bx = bias[n], by = bias[n + 1];
            float v00 = acc[mt][nt][0] + bx, v01 = acc[mt][nt][1] + by;
            float v10 = acc[mt][nt][2] + bx, v11 = acc[mt][nt][3] + by;
            if (MODE == 2) { v00 *= 0.125f; v01 *= 0.125f; v10 *= 0.125f; v11 *= 0.125f; }
            if (MODE >= 1) {
                int h = n >> 6, d = n & 63;
                __half* base = (__half*)Cv + (size_t)(b_idx * NHEAD + h) * (SEQ * DK);
                __half2 h0 = __floats2half2_rn(v00, v01);
                __half2 h1 = __floats2half2_rn(v10, v11);
                *(uint32_t*)&base[(size_t)s_idx * DK + d] = *(uint32_t*)&h0;
                *(uint32_t*)&base[(size_t)(s_idx + 8) * DK + d] = *(uint32_t*)&h1;
            } else {
                float* Cf = (float*)Cv;
                *(float2*)&Cf[(size_t)m * D_MODEL + n] = make_float2(v00, v01);
                *(float2*)&Cf[(size_t)(m + 8) * D_MODEL + n] = make_float2(v10, v11);
            }
        }
    }
}

// ===========================================================================
// Flash attention, fp16 mma, P kept in registers (S C-frag == PV A-frag).
// Block = (bh, 64 q rows), 4 warps x 16 rows. 2-stage cp.async K/V.
// ===========================================================================
#define KVS 72
#define KV_TILE (64 * KVS)
#define F_STAGE (2 * KV_TILE)
#define F_SMEM (2 * F_STAGE * 2)        // 36864 bytes

__global__ __launch_bounds__(128, 3)
void flash_h(const __half* __restrict__ Qh, const __half* __restrict__ Kh,
             const __half* __restrict__ Vh, __half* __restrict__ Out)
{
    extern __shared__ __half sh[];
    const int tid = threadIdx.x;
    const int lane = tid & 31, w = tid >> 5;
    const int g = lane >> 2, q = lane & 3;
    const int qt = blockIdx.x & 31;
    const int bh = blockIdx.x >> 5;
    const int qbase = qt * 64 + w * 16;

    auto load_kv = [&](int kt, int st) {
        __half* Ks = sh + st * F_STAGE;
        __half* Vs = Ks + KV_TILE;
        const __half* kp = Kh + ((size_t)bh * SEQ + kt * 64) * DK;
        const __half* vp = Vh + ((size_t)bh * SEQ + kt * 64) * DK;
        #pragma unroll
        for (int i = 0; i < 4; i++) {
            int j = tid + i * 128;
            int r = j >> 3, c8 = j & 7;
            CP16(smem_u32(&Ks[r * KVS + c8 * 8]), &kp[r * DK + c8 * 8]);
        }
        #pragma unroll
        for (int i = 0; i < 4; i++) {
            int j = tid + i * 128;
            int r = j >> 3, c8 = j & 7;
            CP16(smem_u32(&Vs[r * KVS + c8 * 8]), &vp[r * DK + c8 * 8]);
        }
        CP_COMMIT();
    };

    // Q fragments (pre-scaled at projection), register-resident
    uint32_t Qa[4][4];
    {
        const __half* qp = Qh + ((size_t)bh * SEQ + qbase) * DK;
        #pragma unroll
        for (int ks = 0; ks < 4; ks++) {
            Qa[ks][0] = *(const uint32_t*)&qp[g * DK + ks * 16 + 2 * q];
            Qa[ks][1] = *(const uint32_t*)&qp[(g + 8) * DK + ks * 16 + 2 * q];
            Qa[ks][2] = *(const uint32_t*)&qp[g * DK + ks * 16 + 2 * q + 8];
            Qa[ks][3] = *(const uint32_t*)&qp[(g + 8) * DK + ks * 16 + 2 * q + 8];
        }
    }

    float O[8][4];
    #pragma unroll
    for (int nt = 0; nt < 8; nt++)
        #pragma unroll
        for (int i = 0; i < 4; i++) O[nt][i] = 0.f;
    float m0 = -1e30f, m1 = -1e30f, l0 = 0.f, l1 = 0.f;

    load_kv(0, 0);

    for (int kt = 0; kt < SEQ / 64; kt++) {
        CP_WAIT0();
        __syncthreads();
        if (kt + 1 < SEQ / 64) load_kv(kt + 1, (kt + 1) & 1);

        const __half* Ks = sh + (kt & 1) * F_STAGE;
        const __half* Vs = Ks + KV_TILE;

        // S = Qs @ K^T
        float S[8][4];
        #pragma unroll
        for (int nt = 0; nt < 8; nt++) {
            #pragma unroll
            for (int i = 0; i < 4; i++) S[nt][i] = 0.f;
            #pragma unroll
            for (int ks = 0; ks < 4; ks++) {
                uint32_t bb[2];
                bb[0] = *(const uint32_t*)&Ks[(nt * 8 + g) * KVS + ks * 16 + 2 * q];
                bb[1] = *(const uint32_t*)&Ks[(nt * 8 + g) * KVS + ks * 16 + 2 * q + 8];
                mma_f16(S[nt], Qa[ks], bb);
            }
        }

        // Online softmax
        float mx0 = -1e30f, mx1 = -1e30f;
        #pragma unroll
        for (int nt = 0; nt < 8; nt++) {
            mx0 = fmaxf(mx0, fmaxf(S[nt][0], S[nt][1]));
            mx1 = fmaxf(mx1, fmaxf(S[nt][2], S[nt][3]));
        }
        mx0 = fmaxf(mx0, __shfl_xor_sync(0xFFFFFFFF, mx0, 1));
        mx0 = fmaxf(mx0, __shfl_xor_sync(0xFFFFFFFF, mx0, 2));
        mx1 = fmaxf(mx1, __shfl_xor_sync(0xFFFFFFFF, mx1, 1));
        mx1 = fmaxf(mx1, __shfl_xor_sync(0xFFFFFFFF, mx1, 2));

        float mn0 = fmaxf(m0, mx0), mn1 = fmaxf(m1, mx1);
        float c0 = __expf(m0 - mn0), c1 = __expf(m1 - mn1);
        m0 = mn0; m1 = mn1;

        // P fragments directly in registers: Pa[nt] = {pack(p0,p1), pack(p2,p3)}
        uint32_t Pa[8][2];
        float s0 = 0.f, s1 = 0.f;
        #pragma unroll
        for (int nt = 0; nt < 8; nt++) {
            float p0 = __expf(S[nt][0] - mn0);
            float p1 = __expf(S[nt][1] - mn0);
            float p2 = __expf(S[nt][2] - mn1);
            float p3 = __expf(S[nt][3] - mn1);
            s0 += p0 + p1; s1 += p2 + p3;
            __half2 hp0 = __floats2half2_rn(p0, p1);
            __half2 hp1 = __floats2half2_rn(p2, p3);
            Pa[nt][0] = *(uint32_t*)&hp0;
            Pa[nt][1] = *(uint32_t*)&hp1;
        }
        s0 += __shfl_xor_sync(0xFFFFFFFF, s0, 1);
        s0 += __shfl_xor_sync(0xFFFFFFFF, s0, 2);
        s1 += __shfl_xor_sync(0xFFFFFFFF, s1, 1);
        s1 += __shfl_xor_sync(0xFFFFFFFF, s1, 2);
        l0 = l0 * c0 + s0;
        l1 = l1 * c1 + s1;

        // Rescale O only if some row's max actually moved (rare after warmup)
        if (__ballot_sync(0xFFFFFFFF, (c0 < 1.f) || (c1 < 1.f))) {
            #pragma unroll
            for (int nt = 0; nt < 8; nt++) {
                O[nt][0] *= c0; O[nt][1] *= c0;
                O[nt][2] *= c1; O[nt][3] *= c1;
            }
        }

        // O += P @ V  (V B-frags via ldmatrix.trans; P A-frags from registers)
        #pragma unroll
        for (int ks = 0; ks < 4; ks++) {
            uint32_t pa[4] = { Pa[2 * ks][0], Pa[2 * ks][1],
                               Pa[2 * ks + 1][0], Pa[2 * ks + 1][1] };
            #pragma unroll
            for (int tp = 0; tp < 4; tp++) {
                uint32_t b0, b1, b2, b3;
                int row = ks * 16 + (lane & 15);
                int col = tp * 16 + ((lane >> 4) & 1) * 8;
                ldsm_x4_t(b0, b1, b2, b3, smem_u32(&Vs[row * KVS + col]));
                uint32_t bb0[2] = { b0, b1 }, bb1[2] = { b2, b3 };
                mma_f16(O[2 * tp], pa, bb0);
                mma_f16(O[2 * tp + 1], pa, bb1);
            }
        }
    }

    // Normalize + store half to [B, S, D]
    const float i0 = 1.f / l0, i1 = 1.f / l1;
    const int b_idx = bh >> 4, h_idx = bh & 15;
    __half* op = Out + ((size_t)b_idx * SEQ) * D_MODEL + h_idx * DK;
    #pragma unroll
    for (int nt = 0; nt < 8; nt++) {
        int d = nt * 8 + 2 * q;
        __half2 h0 = __floats2half2_rn(O[nt][0] * i0, O[nt][1] * i0);
        __half2 h1 = __floats2half2_rn(O[nt][2] * i1, O[nt][3] * i1);
        *(uint32_t*)&op[(size_t)(qbase + g) * D_MODEL + d] = *(uint32_t*)&h0;
        *(uint32_t*)&op[(size_t)(qbase + g + 8) * D_MODEL + d] = *(uint32_t*)&h1;
    }
}

// ===========================================================================
extern "C" void kernel_launch(void* const* d_in, const int* in_sizes, int n_in,
                              void* d_out, int out_size)
{
    const float* Q  = (const float*)d_in[0];
    const float* K  = (const float*)d_in[1];
    const float* V  = (const float*)d_in[2];
    const float* Wq = (const float*)d_in[3];
    const float* bq = (const float*)d_in[4];
    const float* Wk = (const float*)d_in[5];
    const float* bk = (const float*)d_in[6];
    const float* Wv = (const float*)d_in[7];
    const float* bv = (const float*)d_in[8];
    const float* Wo = (const float*)d_in[9];
    const float* bo = (const float*)d_in[10];
    float* out = (float*)d_out;

    __half *qi, *ki, *vi, *wh, *qh, *kh, *vh, *ah;
    cudaGetSymbolAddress((void**)&qi, h_qi);
    cudaGetSymbolAddress((void**)&ki, h_ki);
    cudaGetSymbolAddress((void**)&vi, h_vi);
    cudaGetSymbolAddress((void**)&wh, h_w);
    cudaGetSymbolAddress((void**)&qh, h_q);
    cudaGetSymbolAddress((void**)&kh, h_k);
    cudaGetSymbolAddress((void**)&vh, h_v);
    cudaGetSymbolAddress((void**)&ah, h_a);

    cudaFuncSetAttribute(gemm_h<0>, cudaFuncAttributeMaxDynamicSharedMemorySize, G_SMEM);
    cudaFuncSetAttribute(gemm_h<1>, cudaFuncAttributeMaxDynamicSharedMemorySize, G_SMEM);
    cudaFuncSetAttribute(gemm_h<2>, cudaFuncAttributeMaxDynamicSharedMemorySize, G_SMEM);
    cudaFuncSetAttribute(flash_h,   cudaFuncAttributeMaxDynamicSharedMemorySize, F_SMEM);

    const int NI4 = MTOT * D_MODEL / 4;
    const int NW4 = D_MODEL * D_MODEL / 4;
    const size_t WSZ = (size_t)D_MODEL * D_MODEL;

    CvtArgs ca;
    ca.src[0] = (const float4*)Q;  ca.dst[0] = (uint2*)qi;            ca.n4[0] = NI4;
    ca.src[1] = (const float4*)K;  ca.dst[1] = (uint2*)ki;            ca.n4[1] = NI4;
    ca.src[2] = (const float4*)V;  ca.dst[2] = (uint2*)vi;            ca.n4[2] = NI4;
    ca.src[3] = (const float4*)Wq; ca.dst[3] = (uint2*)(wh + 0 * WSZ); ca.n4[3] = NW4;
    ca.src[4] = (const float4*)Wk; ca.dst[4] = (uint2*)(wh + 1 * WSZ); ca.n4[4] = NW4;
    ca.src[5] = (const float4*)Wv; ca.dst[5] = (uint2*)(wh + 2 * WSZ); ca.n4[5] = NW4;
    ca.src[6] = (const float4*)Wo; ca.dst[6] = (uint2*)(wh + 3 * WSZ); ca.n4[6] = NW4;
    f2h_all<<<dim3(512, 7), 256>>>(ca);

    dim3 ggrid(D_MODEL / 128, MTOT / 128);   // (8, 32)
    gemm_h<2><<<ggrid, 256, G_SMEM>>>(qi, wh + 0 * WSZ, bq, qh);  // Q, *0.125
    gemm_h<1><<<ggrid, 256, G_SMEM>>>(ki, wh + 1 * WSZ, bk, kh);
    gemm_h<1><<<ggrid, 256, G_SMEM>>>(vi, wh + 2 * WSZ, bv, vh);

    flash_h<<<BH * (SEQ / 64), 128, F_SMEM>>>(qh, kh, vh, ah);

    gemm_h<0><<<ggrid, 256, G_SMEM>>>(ah, wh + 3 * WSZ, bo, out);
}

// round 6
// speedup vs baseline: 7.7529x; 1.0496x over previous
#include <cuda_runtime.h>
#include <cuda_fp16.h>
#include <stdint.h>

#define D_MODEL 1024
#define NHEAD   16
#define DK      64
#define SEQ     2048
#define BATCH   2
#define MTOT    (BATCH * SEQ)          // 4096
#define BH      (BATCH * NHEAD)        // 32

// --------------------------- device scratch (halfs) ------------------------
__device__ __half h_qi[MTOT * D_MODEL];
__device__ __half h_ki[MTOT * D_MODEL];
__device__ __half h_vi[MTOT * D_MODEL];
__device__ __half h_w[4 * D_MODEL * D_MODEL];
__device__ __half h_q[MTOT * D_MODEL];    // projected, head layout, pre-scaled
__device__ __half h_k[MTOT * D_MODEL];
__device__ __half h_v[MTOT * D_MODEL];
__device__ __half h_a[MTOT * D_MODEL];    // attention out [B,S,D]

// ------------------------------- helpers -----------------------------------
__device__ __forceinline__ uint32_t smem_u32(const void* p) {
    uint32_t a;
    asm("{ .reg .u64 t; cvta.to.shared.u64 t, %1; cvt.u32.u64 %0, t; }"
        : "=r"(a) : "l"(p));
    return a;
}
__device__ __forceinline__ void mma_f16(float* d, const uint32_t* a,
                                        const uint32_t* b) {
    asm volatile(
        "mma.sync.aligned.m16n8k16.row.col.f32.f16.f16.f32 "
        "{%0,%1,%2,%3}, {%4,%5,%6,%7}, {%8,%9}, {%0,%1,%2,%3};"
        : "+f"(d[0]), "+f"(d[1]), "+f"(d[2]), "+f"(d[3])
        : "r"(a[0]), "r"(a[1]), "r"(a[2]), "r"(a[3]), "r"(b[0]), "r"(b[1]));
}
__device__ __forceinline__ void ldsm_x4(uint32_t& d0, uint32_t& d1,
                                        uint32_t& d2, uint32_t& d3,
                                        uint32_t addr) {
    asm volatile("ldmatrix.sync.aligned.m8n8.x4.shared.b16 "
                 "{%0,%1,%2,%3}, [%4];"
                 : "=r"(d0), "=r"(d1), "=r"(d2), "=r"(d3) : "r"(addr));
}
__device__ __forceinline__ void ldsm_x4_t(uint32_t& d0, uint32_t& d1,
                                          uint32_t& d2, uint32_t& d3,
                                          uint32_t addr) {
    asm volatile("ldmatrix.sync.aligned.m8n8.x4.trans.shared.b16 "
                 "{%0,%1,%2,%3}, [%4];"
                 : "=r"(d0), "=r"(d1), "=r"(d2), "=r"(d3) : "r"(addr));
}
#define CP16(dst, src) \
    asm volatile("cp.async.ca.shared.global [%0], [%1], 16;" :: "r"(dst), "l"(src))
#define CP_COMMIT() asm volatile("cp.async.commit_group;")
#define CP_WAIT0()  asm volatile("cp.async.wait_group 0;")
#define CP_WAIT1()  asm volatile("cp.async.wait_group 1;")

// ------------------- fused f32 -> f16 convert (one launch) -----------------
struct CvtArgs {
    const float4* src[7];
    uint2* dst[7];
    int n4[7];
};
__global__ __launch_bounds__(256)
void f2h_all(CvtArgs args)
{
    int seg = blockIdx.y;
    const float4* src = args.src[seg];
    uint2* dst = args.dst[seg];
    int n4 = args.n4[seg];
    for (int i = blockIdx.x * blockDim.x + threadIdx.x; i < n4;
         i += gridDim.x * blockDim.x) {
        float4 v = src[i];
        __half2 a = __floats2half2_rn(v.x, v.y);
        __half2 b = __floats2half2_rn(v.z, v.w);
        uint2 o;
        o.x = *(uint32_t*)&a;
        o.y = *(uint32_t*)&b;
        dst[i] = o;
    }
}

// ===========================================================================
// fp16 tensor-core GEMM body: C[4096,1024] = X @ W[K,N] + bias
// 128x128 CTA tile, 8 warps (32x64 warp tile), k-chunk 32, 3-stage cp.async.
// A and B fragments both via ldmatrix.
// ===========================================================================
#define AH_STRIDE 40
#define BHS 136
#define A_STAGE (128 * AH_STRIDE)
#define B_STAGE (32 * BHS)
#define G_STAGE (A_STAGE + B_STAGE)
#define G_SMEM (3 * G_STAGE * 2)        // 56832 bytes

template <bool HEADOUT>
__device__ __forceinline__
void gemm_body(__half* sh, const __half* __restrict__ X,
               const __half* __restrict__ W, const float* __restrict__ bias,
               void* __restrict__ Cv, float scale)
{
    const int tid = threadIdx.x;
    const int lane = tid & 31, wid = tid >> 5;
    const int g = lane >> 2, q = lane & 3;
    const int m0 = blockIdx.y * 128, n0 = blockIdx.x * 128;
    const int wm = (wid & 3) * 32, wn = (wid >> 2) * 64;

    float acc[2][8][4];
    #pragma unroll
    for (int mt = 0; mt < 2; mt++)
        #pragma unroll
        for (int nt = 0; nt < 8; nt++)
            #pragma unroll
            for (int i = 0; i < 4; i++) acc[mt][nt][i] = 0.f;

    auto load_stage = [&](int c, int st) {
        __half* As = sh + st * G_STAGE;
        __half* Bs = As + A_STAGE;
        int k0 = c * 32;
        #pragma unroll
        for (int i = 0; i < 2; i++) {
            int j = tid + i * 256;
            int r = j >> 2, c8 = j & 3;
            CP16(smem_u32(&As[r * AH_STRIDE + c8 * 8]),
                 &X[(size_t)(m0 + r) * D_MODEL + k0 + c8 * 8]);
        }
        #pragma unroll
        for (int i = 0; i < 2; i++) {
            int j = tid + i * 256;
            int r = j >> 4, c8 = j & 15;
            CP16(smem_u32(&Bs[r * BHS + c8 * 8]),
                 &W[(size_t)(k0 + r) * D_MODEL + n0 + c8 * 8]);
        }
        CP_COMMIT();
    };

    load_stage(0, 0);
    load_stage(1, 1);

    // ldmatrix lane->row mapping (A, non-trans x4):
    // matrices: (rows0-7,k0-7)(rows8-15,k0-7)(rows0-7,k8-15)(rows8-15,k8-15)
    const int a_row = ((lane >> 3) & 1) * 8 + (lane & 7);
    const int a_kof = (lane >> 4) * 8;

    for (int c = 0; c < 32; c++) {
        const int st = c % 3;
        if (c < 31) { CP_WAIT1(); } else { CP_WAIT0(); }
        __syncthreads();
        if (c + 2 < 32) load_stage(c + 2, (c + 2) % 3);

        const __half* As = sh + st * G_STAGE;
        const __half* Bs = As + A_STAGE;
        #pragma unroll
        for (int ks = 0; ks < 2; ks++) {
            uint32_t af[2][4];
            #pragma unroll
            for (int mt = 0; mt < 2; mt++) {
                ldsm_x4(af[mt][0], af[mt][1], af[mt][2], af[mt][3],
                        smem_u32(&As[(wm + mt * 16 + a_row) * AH_STRIDE
                                     + ks * 16 + a_kof]));
            }
            #pragma unroll
            for (int tp = 0; tp < 4; tp++) {
                uint32_t b0, b1, b2, b3;
                int row = ks * 16 + (lane & 15);
                int col = wn + tp * 16 + ((lane >> 4) & 1) * 8;
                ldsm_x4_t(b0, b1, b2, b3, smem_u32(&Bs[row * BHS + col]));
                uint32_t bb0[2] = { b0, b1 }, bb1[2] = { b2, b3 };
                mma_f16(acc[0][2 * tp], af[0], bb0);
                mma_f16(acc[1][2 * tp], af[1], bb0);
                mma_f16(acc[0][2 * tp + 1], af[0], bb1);
                mma_f16(acc[1][2 * tp + 1], af[1], bb1);
            }
        }
    }

    // Epilogue
    #pragma unroll
    for (int mt = 0; mt < 2; mt++) {
        int m = m0 + wm + mt * 16 + g;
        int b_idx = m >> 11, s_idx = m & 2047;
        #pragma unroll
        for (int nt = 0; nt < 8; nt++) {
            int n = n0 + wn + nt * 8 + 2 * q;
            float bx = bias[n], by = bias[n + 1];
            float v00 = (acc[mt][nt][0] + bx) * scale;
            float v01 = (acc[mt][nt][1] + by) * scale;
            float v10 = (acc[mt][nt][2] + bx) * scale;
            float v11 = (acc[mt][nt][3] + by) * scale;
            if (HEADOUT) {
                int h = n >> 6, d = n & 63;
                __half* base = (__half*)Cv + (size_t)(b_idx * NHEAD + h) * (SEQ * DK);
                __half2 h0 = __floats2half2_rn(v00, v01);
                __half2 h1 = __floats2half2_rn(v10, v11);
                *(uint32_t*)&base[(size_t)s_idx * DK + d] = *(uint32_t*)&h0;
                *(uint32_t*)&base[(size_t)(s_idx + 8) * DK + d] = *(uint32_t*)&h1;
            } else {
                float* Cf = (float*)Cv;
                *(float2*)&Cf[(size_t)m * D_MODEL + n] = make_float2(v00, v01);
                *(float2*)&Cf[(size_t)(m + 8) * D_MODEL + n] = make_float2(v10, v11);
            }
        }
    }
}

// Fused QKV projection: blockIdx.z selects (X, W, bias, out, scale)
struct QKVArgs {
    const __half* X[3];
    const __half* W[3];
    const float* b[3];
    __half* C[3];
    float scale[3];
};
__global__ __launch_bounds__(256, 2)
void gemm_qkv(QKVArgs a)
{
    extern __shared__ __half sh[];
    int z = blockIdx.z;
    gemm_body<true>(sh, a.X[z], a.W[z], a.b[z], a.C[z], a.scale[z]);
}

__global__ __launch_bounds__(256, 2)
void gemm_out(const __half* __restrict__ X, const __half* __restrict__ W,
              const float* __restrict__ bias, float* __restrict__ C)
{
    extern __shared__ __half sh[];
    gemm_body<false>(sh, X, W, bias, C, 1.f);
}

// ===========================================================================
// Flash attention, fp16 mma, P in registers, K/V frags via ldmatrix.
// Block = (bh, 64 q rows), 4 warps x 16 rows. 2-stage cp.async K/V.
// ===========================================================================
#define KVS 72
#define KV_TILE (64 * KVS)
#define F_STAGE (2 * KV_TILE)
#define F_SMEM (2 * F_STAGE * 2)        // 36864 bytes

__global__ __launch_bounds__(128, 3)
void flash_h(const __half* __restrict__ Qh, const __half* __restrict__ Kh,
             const __half* __restrict__ Vh, __half* __restrict__ Out)
{
    extern __shared__ __half sh[];
    const int tid = threadIdx.x;
    const int lane = tid & 31, w = tid >> 5;
    const int g = lane >> 2, q = lane & 3;
    const int qt = blockIdx.x & 31;
    const int bh = blockIdx.x >> 5;
    const int qbase = qt * 64 + w * 16;

    auto load_kv = [&](int kt, int st) {
        __half* Ks = sh + st * F_STAGE;
        __half* Vs = Ks + KV_TILE;
        const __half* kp = Kh + ((size_t)bh * SEQ + kt * 64) * DK;
        const __half* vp = Vh + ((size_t)bh * SEQ + kt * 64) * DK;
        #pragma unroll
        for (int i = 0; i < 4; i++) {
            int j = tid + i * 128;
            int r = j >> 3, c8 = j & 7;
            CP16(smem_u32(&Ks[r * KVS + c8 * 8]), &kp[r * DK + c8 * 8]);
        }
        #pragma unroll
        for (int i = 0; i < 4; i++) {
            int j = tid + i * 128;
            int r = j >> 3, c8 = j & 7;
            CP16(smem_u32(&Vs[r * KVS + c8 * 8]), &vp[r * DK + c8 * 8]);
        }
        CP_COMMIT();
    };

    // Q fragments (pre-scaled at projection), register-resident
    uint32_t Qa[4][4];
    {
        const __half* qp = Qh + ((size_t)bh * SEQ + qbase) * DK;
        #pragma unroll
        for (int ks = 0; ks < 4; ks++) {
            Qa[ks][0] = *(const uint32_t*)&qp[g * DK + ks * 16 + 2 * q];
            Qa[ks][1] = *(const uint32_t*)&qp[(g + 8) * DK + ks * 16 + 2 * q];
            Qa[ks][2] = *(const uint32_t*)&qp[g * DK + ks * 16 + 2 * q + 8];
            Qa[ks][3] = *(const uint32_t*)&qp[(g + 8) * DK + ks * 16 + 2 * q + 8];
        }
    }

    float O[8][4];
    #pragma unroll
    for (int nt = 0; nt < 8; nt++)
        #pragma unroll
        for (int i = 0; i < 4; i++) O[nt][i] = 0.f;
    float m0 = -1e30f, m1 = -1e30f, l0 = 0.f, l1 = 0.f;

    load_kv(0, 0);

    // K ldmatrix addressing (non-trans x4):
    // matrices (n0-7,k0-7)(n0-7,k8-15)(n8-15,k0-7)(n8-15,k8-15)
    const int k_nrow = (lane >> 4) * 8 + (lane & 7);
    const int k_kof = ((lane >> 3) & 1) * 8;

    for (int kt = 0; kt < SEQ / 64; kt++) {
        CP_WAIT0();
        __syncthreads();
        if (kt + 1 < SEQ / 64) load_kv(kt + 1, (kt + 1) & 1);

        const __half* Ks = sh + (kt & 1) * F_STAGE;
        const __half* Vs = Ks + KV_TILE;

        // S = Qs @ K^T (K B-frags via ldmatrix non-trans)
        float S[8][4];
        #pragma unroll
        for (int nt = 0; nt < 8; nt++)
            #pragma unroll
            for (int i = 0; i < 4; i++) S[nt][i] = 0.f;
        #pragma unroll
        for (int ks = 0; ks < 4; ks++) {
            #pragma unroll
            for (int ntp = 0; ntp < 4; ntp++) {
                uint32_t b0, b1, b2, b3;
                ldsm_x4(b0, b1, b2, b3,
                        smem_u32(&Ks[(ntp * 16 + k_nrow) * KVS + ks * 16 + k_kof]));
                uint32_t bb0[2] = { b0, b1 }, bb1[2] = { b2, b3 };
                mma_f16(S[2 * ntp], Qa[ks], bb0);
                mma_f16(S[2 * ntp + 1], Qa[ks], bb1);
            }
        }

        // Online softmax
        float mx0 = -1e30f, mx1 = -1e30f;
        #pragma unroll
        for (int nt = 0; nt < 8; nt++) {
            mx0 = fmaxf(mx0, fmaxf(S[nt][0], S[nt][1]));
            mx1 = fmaxf(mx1, fmaxf(S[nt][2], S[nt][3]));
        }
        mx0 = fmaxf(mx0, __shfl_xor_sync(0xFFFFFFFF, mx0, 1));
        mx0 = fmaxf(mx0, __shfl_xor_sync(0xFFFFFFFF, mx0, 2));
        mx1 = fmaxf(mx1, __shfl_xor_sync(0xFFFFFFFF, mx1, 1));
        mx1 = fmaxf(mx1, __shfl_xor_sync(0xFFFFFFFF, mx1, 2));

        float mn0 = fmaxf(m0, mx0), mn1 = fmaxf(m1, mx1);
        float c0 = __expf(m0 - mn0), c1 = __expf(m1 - mn1);
        m0 = mn0; m1 = mn1;

        uint32_t Pa[8][2];
        float s0 = 0.f, s1 = 0.f;
        #pragma unroll
        for (int nt = 0; nt < 8; nt++) {
            float p0 = __expf(S[nt][0] - mn0);
            float p1 = __expf(S[nt][1] - mn0);
            float p2 = __expf(S[nt][2] - mn1);
            float p3 = __expf(S[nt][3] - mn1);
            s0 += p0 + p1; s1 += p2 + p3;
            __half2 hp0 = __floats2half2_rn(p0, p1);
            __half2 hp1 = __floats2half2_rn(p2, p3);
            Pa[nt][0] = *(uint32_t*)&hp0;
            Pa[nt][1] = *(uint32_t*)&hp1;
        }
        s0 += __shfl_xor_sync(0xFFFFFFFF, s0, 1);
        s0 += __shfl_xor_sync(0xFFFFFFFF, s0, 2);
        s1 += __shfl_xor_sync(0xFFFFFFFF, s1, 1);
        s1 += __shfl_xor_sync(0xFFFFFFFF, s1, 2);
        l0 = l0 * c0 + s0;
        l1 = l1 * c1 + s1;

        if (__ballot_sync(0xFFFFFFFF, (c0 < 1.f) || (c1 < 1.f))) {
            #pragma unroll
            for (int nt = 0; nt < 8; nt++) {
                O[nt][0] *= c0; O[nt][1] *= c0;
                O[nt][2] *= c1; O[nt][3] *= c1;
            }
        }

        // O += P @ V
        #pragma unroll
        for (int ks = 0; ks < 4; ks++) {
            uint32_t pa[4] = { Pa[2 * ks][0], Pa[2 * ks][1],
                               Pa[2 * ks + 1][0], Pa[2 * ks + 1][1] };
            #pragma unroll
            for (int tp = 0; tp < 4; tp++) {
                uint32_t b0, b1, b2, b3;
                int row = ks * 16 + (lane & 15);
                int col = tp * 16 + ((lane >> 4) & 1) * 8;
                ldsm_x4_t(b0, b1, b2, b3, smem_u32(&Vs[row * KVS + col]));
                uint32_t bb0[2] = { b0, b1 }, bb1[2] = { b2, b3 };
                mma_f16(O[2 * tp], pa, bb0);
                mma_f16(O[2 * tp + 1], pa, bb1);
            }
        }
    }

    // Normalize + store half to [B, S, D]
    const float i0 = 1.f / l0, i1 = 1.f / l1;
    const int b_idx = bh >> 4, h_idx = bh & 15;
    __half* op = Out + ((size_t)b_idx * SEQ) * D_MODEL + h_idx * DK;
    #pragma unroll
    for (int nt = 0; nt < 8; nt++) {
        int d = nt * 8 + 2 * q;
        __half2 h0 = __floats2half2_rn(O[nt][0] * i0, O[nt][1] * i0);
        __half2 h1 = __floats2half2_rn(O[nt][2] * i1, O[nt][3] * i1);
        *(uint32_t*)&op[(size_t)(qbase + g) * D_MODEL + d] = *(uint32_t*)&h0;
        *(uint32_t*)&op[(size_t)(qbase + g + 8) * D_MODEL + d] = *(uint32_t*)&h1;
    }
}

// ===========================================================================
extern "C" void kernel_launch(void* const* d_in, const int* in_sizes, int n_in,
                              void* d_out, int out_size)
{
    const float* Q  = (const float*)d_in[0];
    const float* K  = (const float*)d_in[1];
    const float* V  = (const float*)d_in[2];
    const float* Wq = (const float*)d_in[3];
    const float* bq = (const float*)d_in[4];
    const float* Wk = (const float*)d_in[5];
    const float* bk = (const float*)d_in[6];
    const float* Wv = (const float*)d_in[7];
    const float* bv = (const float*)d_in[8];
    const float* Wo = (const float*)d_in[9];
    const float* bo = (const float*)d_in[10];
    float* out = (float*)d_out;

    __half *qi, *ki, *vi, *wh, *qh, *kh, *vh, *ah;
    cudaGetSymbolAddress((void**)&qi, h_qi);
    cudaGetSymbolAddress((void**)&ki, h_ki);
    cudaGetSymbolAddress((void**)&vi, h_vi);
    cudaGetSymbolAddress((void**)&wh, h_w);
    cudaGetSymbolAddress((void**)&qh, h_q);
    cudaGetSymbolAddress((void**)&kh, h_k);
    cudaGetSymbolAddress((void**)&vh, h_v);
    cudaGetSymbolAddress((void**)&ah, h_a);

    cudaFuncSetAttribute(gemm_qkv, cudaFuncAttributeMaxDynamicSharedMemorySize, G_SMEM);
    cudaFuncSetAttribute(gemm_out, cudaFuncAttributeMaxDynamicSharedMemorySize, G_SMEM);
    cudaFuncSetAttribute(flash_h,  cudaFuncAttributeMaxDynamicSharedMemorySize, F_SMEM);

    const int NI4 = MTOT * D_MODEL / 4;
    const int NW4 = D_MODEL * D_MODEL / 4;
    const size_t WSZ = (size_t)D_MODEL * D_MODEL;

    CvtArgs ca;
    ca.src[0] = (const float4*)Q;  ca.dst[0] = (uint2*)qi;             ca.n4[0] = NI4;
    ca.src[1] = (const float4*)K;  ca.dst[1] = (uint2*)ki;             ca.n4[1] = NI4;
    ca.src[2] = (const float4*)V;  ca.dst[2] = (uint2*)vi;             ca.n4[2] = NI4;
    ca.src[3] = (const float4*)Wq; ca.dst[3] = (uint2*)(wh + 0 * WSZ); ca.n4[3] = NW4;
    ca.src[4] = (const float4*)Wk; ca.dst[4] = (uint2*)(wh + 1 * WSZ); ca.n4[4] = NW4;
    ca.src[5] = (const float4*)Wv; ca.dst[5] = (uint2*)(wh + 2 * WSZ); ca.n4[5] = NW4;
    ca.src[6] = (const float4*)Wo; ca.dst[6] = (uint2*)(wh + 3 * WSZ); ca.n4[6] = NW4;
    f2h_all<<<dim3(512, 7), 256>>>(ca);

    QKVArgs qa;
    qa.X[0] = qi; qa.W[0] = wh + 0 * WSZ; qa.b[0] = bq; qa.C[0] = qh; qa.scale[0] = 0.125f;
    qa.X[1] = ki; qa.W[1] = wh + 1 * WSZ; qa.b[1] = bk; qa.C[1] = kh; qa.scale[1] = 1.f;
    qa.X[2] = vi; qa.W[2] = wh + 2 * WSZ; qa.b[2] = bv; qa.C[2] = vh; qa.scale[2] = 1.f;

    dim3 ggrid(D_MODEL / 128, MTOT / 128, 3);   // (8, 32, 3)
    gemm_qkv<<<ggrid, 256, G_SMEM>>>(qa);

    flash_h<<<BH * (SEQ / 64), 128, F_SMEM>>>(qh, kh, vh, ah);

    dim3 ogrid(D_MODEL / 128, MTOT / 128);
    gemm_out<<<ogrid, 256, G_SMEM>>>(ah, wh + 3 * WSZ, bo, out);
}